// round 1
// baseline (speedup 1.0000x reference)
#include <cuda_runtime.h>
#include <math.h>

// Problem constants (fixed by setup_inputs)
#define LQ   4096      // query rows
#define DD   2048      // feature dim
#define TT   4096      // kv tokens
#define WIN  1024      // sliding window

// Scratch (device globals — no allocation APIs allowed)
__device__ float g_Q[(size_t)LQ * DD];   // 32 MB
__device__ float g_S[(size_t)LQ * TT];   // 64 MB (scores, then probs in-place)

// ---------------------------------------------------------------------------
// NT GEMM: C[M,N] = A[M,K] * B[N,K]^T   (both row-major, K contiguous)
// 128x128 tile, BK=8, 256 threads, 8x8 per-thread micro-tile.
// BAND: skip tiles fully outside the sliding window (uses block row/col).
// SCALE: multiply output by `scale`.
// ---------------------------------------------------------------------------
template<bool BAND, bool SCALE>
__global__ __launch_bounds__(256)
void gemm_nt(const float* __restrict__ A, const float* __restrict__ B,
             float* __restrict__ C, int M, int N, int K, float scale)
{
    const int bm = blockIdx.y, bn = blockIdx.x;
    if (BAND) {
        const int r0 = bm << 7, c0 = bn << 7;
        int dist = 0;
        if (c0 > r0 + 127)      dist = c0 - (r0 + 127);
        else if (r0 > c0 + 127) dist = r0 - (c0 + 127);
        if (dist >= WIN) return;   // tile entirely masked
    }
    __shared__ float As[8][128];
    __shared__ float Bs[8][128];

    const int tid  = threadIdx.x;
    const int tx   = tid & 15, ty = tid >> 4;
    const int lrow = tid >> 1, kg = (tid & 1) << 2;

    const float* Ap = A + (size_t)(bm * 128 + lrow) * K + kg;
    const float* Bp = B + (size_t)(bn * 128 + lrow) * K + kg;

    float acc[8][8] = {};

    for (int kt = 0; kt < K; kt += 8) {
        const float4 av = *(const float4*)(Ap + kt);
        const float4 bv = *(const float4*)(Bp + kt);
        __syncthreads();
        As[kg + 0][lrow] = av.x; As[kg + 1][lrow] = av.y;
        As[kg + 2][lrow] = av.z; As[kg + 3][lrow] = av.w;
        Bs[kg + 0][lrow] = bv.x; Bs[kg + 1][lrow] = bv.y;
        Bs[kg + 2][lrow] = bv.z; Bs[kg + 3][lrow] = bv.w;
        __syncthreads();
        #pragma unroll
        for (int k = 0; k < 8; k++) {
            const float4 a0 = *(const float4*)&As[k][ty * 8];
            const float4 a1 = *(const float4*)&As[k][ty * 8 + 4];
            const float4 b0 = *(const float4*)&Bs[k][tx * 8];
            const float4 b1 = *(const float4*)&Bs[k][tx * 8 + 4];
            const float a[8] = {a0.x, a0.y, a0.z, a0.w, a1.x, a1.y, a1.z, a1.w};
            const float b[8] = {b0.x, b0.y, b0.z, b0.w, b1.x, b1.y, b1.z, b1.w};
            #pragma unroll
            for (int i = 0; i < 8; i++)
                #pragma unroll
                for (int j = 0; j < 8; j++)
                    acc[i][j] = fmaf(a[i], b[j], acc[i][j]);
        }
    }
    const float s = SCALE ? scale : 1.0f;
    #pragma unroll
    for (int i = 0; i < 8; i++) {
        float* Cp = C + (size_t)(bm * 128 + ty * 8 + i) * N + bn * 128 + tx * 8;
        #pragma unroll
        for (int j = 0; j < 8; j += 4) {
            float4 v = make_float4(acc[i][j] * s, acc[i][j+1] * s,
                                   acc[i][j+2] * s, acc[i][j+3] * s);
            *(float4*)(Cp + j) = v;
        }
    }
}

// ---------------------------------------------------------------------------
// NN GEMM: C[M,N] = A[M,K] * B[K,N]   (row-major). Same tiling.
// BAND: per row-block, restrict K loop to the union of the rows' windows
// (A entries outside each row's personal window are exactly zero).
// ---------------------------------------------------------------------------
template<bool BAND>
__global__ __launch_bounds__(256)
void gemm_nn(const float* __restrict__ A, const float* __restrict__ B,
             float* __restrict__ C, int M, int N, int K)
{
    const int bm = blockIdx.y, bn = blockIdx.x;
    int k0 = 0, kend = K;
    if (BAND) {
        k0 = bm * 128 - (WIN - 1);
        if (k0 < 0) k0 = 0;
        k0 &= ~7;
        kend = bm * 128 + 127 + (WIN - 1) + 1;
        kend = (kend + 7) & ~7;
        if (kend > K) kend = K;
    }
    __shared__ float As[8][128];
    __shared__ float Bs[8][128];

    const int tid  = threadIdx.x;
    const int tx   = tid & 15, ty = tid >> 4;
    const int lrow = tid >> 1, kg = (tid & 1) << 2;
    const int bk   = tid >> 5, bn4 = (tid & 31) << 2;

    const float* Ap = A + (size_t)(bm * 128 + lrow) * K + kg;
    const float* Bp = B + (size_t)(bn * 128) + bn4;

    float acc[8][8] = {};

    for (int kt = k0; kt < kend; kt += 8) {
        const float4 av = *(const float4*)(Ap + kt);
        const float4 bv = *(const float4*)(Bp + (size_t)(kt + bk) * N);
        __syncthreads();
        As[kg + 0][lrow] = av.x; As[kg + 1][lrow] = av.y;
        As[kg + 2][lrow] = av.z; As[kg + 3][lrow] = av.w;
        *(float4*)&Bs[bk][bn4] = bv;
        __syncthreads();
        #pragma unroll
        for (int k = 0; k < 8; k++) {
            const float4 a0 = *(const float4*)&As[k][ty * 8];
            const float4 a1 = *(const float4*)&As[k][ty * 8 + 4];
            const float4 b0 = *(const float4*)&Bs[k][tx * 8];
            const float4 b1 = *(const float4*)&Bs[k][tx * 8 + 4];
            const float a[8] = {a0.x, a0.y, a0.z, a0.w, a1.x, a1.y, a1.z, a1.w};
            const float b[8] = {b0.x, b0.y, b0.z, b0.w, b1.x, b1.y, b1.z, b1.w};
            #pragma unroll
            for (int i = 0; i < 8; i++)
                #pragma unroll
                for (int j = 0; j < 8; j++)
                    acc[i][j] = fmaf(a[i], b[j], acc[i][j]);
        }
    }
    #pragma unroll
    for (int i = 0; i < 8; i++) {
        float* Cp = C + (size_t)(bm * 128 + ty * 8 + i) * N + bn * 128 + tx * 8;
        #pragma unroll
        for (int j = 0; j < 8; j += 4) {
            float4 v = make_float4(acc[i][j], acc[i][j+1], acc[i][j+2], acc[i][j+3]);
            *(float4*)(Cp + j) = v;
        }
    }
}

// ---------------------------------------------------------------------------
// Row softmax over the sliding-window band; writes full dense row of probs
// (zeros outside the band) in-place.
// ---------------------------------------------------------------------------
__global__ __launch_bounds__(256)
void softmax_rows(float* __restrict__ S)
{
    const int row = blockIdx.x;
    const int lo  = max(0, row - (WIN - 1));
    const int hi  = min(TT - 1, row + (WIN - 1));
    float* sr = S + (size_t)row * TT;

    __shared__ float red[256];
    const int tid = threadIdx.x;

    float mx = -3.402823e38f;
    for (int t = lo + tid; t <= hi; t += 256) mx = fmaxf(mx, sr[t]);
    red[tid] = mx; __syncthreads();
    #pragma unroll
    for (int s = 128; s > 0; s >>= 1) {
        if (tid < s) red[tid] = fmaxf(red[tid], red[tid + s]);
        __syncthreads();
    }
    mx = red[0]; __syncthreads();

    float sum = 0.0f;
    for (int t = lo + tid; t <= hi; t += 256) sum += expf(sr[t] - mx);
    red[tid] = sum; __syncthreads();
    #pragma unroll
    for (int s = 128; s > 0; s >>= 1) {
        if (tid < s) red[tid] += red[tid + s];
        __syncthreads();
    }
    const float inv = 1.0f / red[0];

    for (int t = tid; t < TT; t += 256) {
        float v = 0.0f;
        if (t >= lo && t <= hi) v = expf(sr[t] - mx) * inv;
        sr[t] = v;
    }
}

// ---------------------------------------------------------------------------
extern "C" void kernel_launch(void* const* d_in, const int* in_sizes, int n_in,
                              void* d_out, int out_size)
{
    const float* x  = (const float*)d_in[0];   // (L, d)
    const float* Wq = (const float*)d_in[1];   // (d, d)
    const float* Pk = (const float*)d_in[2];   // (1, T, d)
    const float* Pv = (const float*)d_in[3];   // (1, T, d)
    float* out = (float*)d_out;                // (1, L, d)

    float* Q; float* S;
    cudaGetSymbolAddress((void**)&Q, g_Q);
    cudaGetSymbolAddress((void**)&S, g_S);

    const float scale = 1.0f / sqrtf((float)DD);
    dim3 blk(256);

    // 1) Q = x @ Wq^T
    gemm_nt<false, false><<<dim3(DD / 128, LQ / 128), blk>>>(x, Wq, Q, LQ, DD, DD, 1.0f);
    // 2) S = (Q @ Pk^T) * scale, band tiles only
    gemm_nt<true, true><<<dim3(TT / 128, LQ / 128), blk>>>(Q, Pk, S, LQ, TT, DD, scale);
    // 3) row softmax over band, dense probs with zeros outside
    softmax_rows<<<LQ, blk>>>(S);
    // 4) y = P @ Pv, K restricted to band union per row-block
    gemm_nn<true><<<dim3(DD / 128, LQ / 128), blk>>>(S, Pv, out, LQ, DD, TT);
}

// round 7
// speedup vs baseline: 3.5678x; 3.5678x over previous
#include <cuda_runtime.h>
#include <math.h>
#include <stdint.h>

#define LQ  4096
#define DD  2048
#define TT  4096
#define WIN 1024

// ---------------- scratch (device globals; no allocation APIs) --------------
__device__ float g_Q [(size_t)LQ * DD];   // 32 MB
__device__ float g_S [(size_t)LQ * TT];   // 64 MB: scores, then probs in-place
__device__ float g_VT[(size_t)DD * TT];   // 64 MB: Pv^T

// ---------------- PTX helpers ----------------------------------------------
__device__ __forceinline__ uint32_t f2tf(float f) {
    uint32_t r; asm("cvt.rna.tf32.f32 %0, %1;" : "=r"(r) : "f"(f)); return r;
}
__device__ __forceinline__ void mma_tf32(float* c, const uint32_t* a, const uint32_t* b) {
    asm volatile("mma.sync.aligned.m16n8k8.row.col.f32.tf32.tf32.f32 "
                 "{%0,%1,%2,%3}, {%4,%5,%6,%7}, {%8,%9}, {%0,%1,%2,%3};"
                 : "+f"(c[0]), "+f"(c[1]), "+f"(c[2]), "+f"(c[3])
                 : "r"(a[0]), "r"(a[1]), "r"(a[2]), "r"(a[3]),
                   "r"(b[0]), "r"(b[1]));
}
__device__ __forceinline__ uint32_t smem_u32(const void* p) {
    uint32_t a;
    asm("{ .reg .u64 t; cvta.to.shared.u64 t, %1; cvt.u32.u64 %0, t; }"
        : "=r"(a) : "l"(p));
    return a;
}
#define CP_ASYNC16(dst, src) \
    asm volatile("cp.async.cg.shared.global [%0], [%1], 16;" :: "r"(dst), "l"(src))
#define CP_COMMIT() asm volatile("cp.async.commit_group;" ::: "memory")
#define CP_WAIT(n)  asm volatile("cp.async.wait_group %0;" :: "n"(n) : "memory")

// ---------------- tf32 NT GEMM: C[M,N] = A[M,K] * B[N,K]^T ------------------
// 128x128 CTA tile, BK=32, cp.async double buffer, 256 thr, 8 warps of 64x32.
// Smem tiles padded to stride 36 floats (conflict-free frag LDS, 16B-aligned).
// BAND   : skip tiles fully outside sliding window (scores GEMM).
// KRANGE : restrict K loop to band union per row-block (output GEMM).
static constexpr int PAD = 36;
static constexpr int TILE_F = 128 * PAD;              // floats per tile
static constexpr int SMEM_F = 2 * 2 * TILE_F;         // 2 bufs x (A,B)
static constexpr int SMEM_B = SMEM_F * 4;             // 73728 bytes

template<bool BAND, bool KRANGE>
__global__ __launch_bounds__(256, 2)
void tf32_gemm_nt(const float* __restrict__ A, const float* __restrict__ B,
                  float* __restrict__ C, int Ntot, int Ktot, float scale)
{
    const int bm = blockIdx.y, bn = blockIdx.x;
    if (BAND) {
        const int r0 = bm << 7, c0 = bn << 7;
        int dist = 0;
        if (c0 > r0 + 127)      dist = c0 - (r0 + 127);
        else if (r0 > c0 + 127) dist = r0 - (c0 + 127);
        if (dist >= WIN) return;
    }
    int k0 = 0, kend = Ktot;
    if (KRANGE) {
        k0 = bm * 128 - (WIN - 1); if (k0 < 0) k0 = 0; k0 &= ~31;
        kend = bm * 128 + 127 + WIN;
        kend = (kend + 31) & ~31; if (kend > Ktot) kend = Ktot;
    }
    const int nT = (kend - k0) >> 5;

    extern __shared__ float sm[];
    const int tid = threadIdx.x, lane = tid & 31, w = tid >> 5;
    const int wm = (w & 1) * 64, wn = (w >> 1) * 32;

    // staging map: float4 u -> (row = u>>3, c4 = u&7)
    const int srow = tid >> 3, sc4 = tid & 7;
    const float* Ag = A + (size_t)(bm * 128) * Ktot + k0;
    const float* Bg = B + (size_t)(bn * 128) * Ktot + k0;

    auto stage = [&](int t, int buf) {
        float* As = sm + buf * (2 * TILE_F);
        float* Bs = As + TILE_F;
        const int kb = t << 5;
        #pragma unroll
        for (int i = 0; i < 4; i++) {
            const int r = srow + i * 32;
            uint32_t da = smem_u32(As + r * PAD + sc4 * 4);
            uint32_t db = smem_u32(Bs + r * PAD + sc4 * 4);
            CP_ASYNC16(da, Ag + (size_t)r * Ktot + kb + sc4 * 4);
            CP_ASYNC16(db, Bg + (size_t)r * Ktot + kb + sc4 * 4);
        }
        CP_COMMIT();
    };

    float acc[4][4][4] = {};
    const int ar = wm + (lane >> 2);   // + mi*16 (+8)
    const int ac = lane & 3;           // + ks*8 (+4)
    const int br = wn + (lane >> 2);   // + ni*8

    stage(0, 0);

    for (int t = 0; t < nT; t++) {
        const int buf = t & 1;
        if (t + 1 < nT) { stage(t + 1, buf ^ 1); CP_WAIT(1); }
        else            { CP_WAIT(0); }
        __syncthreads();

        const float* As = sm + buf * (2 * TILE_F);
        const float* Bs = As + TILE_F;
        #pragma unroll
        for (int ks = 0; ks < 4; ks++) {
            uint32_t af[4][4], bf[4][2];
            #pragma unroll
            for (int mi = 0; mi < 4; mi++) {
                const float* ap = As + (ar + mi * 16) * PAD + ks * 8 + ac;
                af[mi][0] = f2tf(ap[0]);
                af[mi][1] = f2tf(ap[8 * PAD]);
                af[mi][2] = f2tf(ap[4]);
                af[mi][3] = f2tf(ap[8 * PAD + 4]);
            }
            #pragma unroll
            for (int ni = 0; ni < 4; ni++) {
                const float* bp = Bs + (br + ni * 8) * PAD + ks * 8 + ac;
                bf[ni][0] = f2tf(bp[0]);
                bf[ni][1] = f2tf(bp[4]);
            }
            #pragma unroll
            for (int mi = 0; mi < 4; mi++)
                #pragma unroll
                for (int ni = 0; ni < 4; ni++)
                    mma_tf32(acc[mi][ni], af[mi], bf[ni]);
        }
        __syncthreads();
    }

    // epilogue
    #pragma unroll
    for (int mi = 0; mi < 4; mi++) {
        const int row = bm * 128 + wm + mi * 16 + (lane >> 2);
        #pragma unroll
        for (int ni = 0; ni < 4; ni++) {
            const int col = bn * 128 + wn + ni * 8 + 2 * (lane & 3);
            float2* p0 = (float2*)(C + (size_t)row * Ntot + col);
            float2* p1 = (float2*)(C + (size_t)(row + 8) * Ntot + col);
            *p0 = make_float2(acc[mi][ni][0] * scale, acc[mi][ni][1] * scale);
            *p1 = make_float2(acc[mi][ni][2] * scale, acc[mi][ni][3] * scale);
        }
    }
}

// ---------------- Pv [T][D] -> Pv^T [D][T] (fp32) ---------------------------
__global__ __launch_bounds__(256)
void k_transpose(const float* __restrict__ in, float* __restrict__ out)
{
    __shared__ float t[32][33];
    const int bx = blockIdx.x;   // T tile
    const int by = blockIdx.y;   // D tile
    const int tx = threadIdx.x, ty0 = threadIdx.y;
    #pragma unroll
    for (int i = 0; i < 4; i++) {
        int ty = ty0 + i * 8;
        t[ty][tx] = in[(size_t)(bx * 32 + ty) * DD + by * 32 + tx];
    }
    __syncthreads();
    #pragma unroll
    for (int i = 0; i < 4; i++) {
        int ty = ty0 + i * 8;
        out[(size_t)(by * 32 + ty) * TT + bx * 32 + tx] = t[tx][ty];
    }
}

// ---------------- banded softmax, fp32 in place (zeros outside band) --------
__global__ __launch_bounds__(256)
void k_softmax(float* __restrict__ S)
{
    const int row = blockIdx.x;
    const int lo  = max(0, row - (WIN - 1));
    const int hi  = min(TT - 1, row + (WIN - 1));
    float* sr = S + (size_t)row * TT;

    __shared__ float red[256];
    const int tid = threadIdx.x;

    float mx = -3.402823e38f;
    for (int t = lo + tid; t <= hi; t += 256) mx = fmaxf(mx, sr[t]);
    red[tid] = mx; __syncthreads();
    #pragma unroll
    for (int s = 128; s > 0; s >>= 1) {
        if (tid < s) red[tid] = fmaxf(red[tid], red[tid + s]);
        __syncthreads();
    }
    mx = red[0]; __syncthreads();

    float e[8];
    float sum = 0.0f;
    {
        int j = 0;
        for (int t = lo + tid; t <= hi; t += 256, j++) {
            float ev = __expf(sr[t] - mx);
            e[j] = ev; sum += ev;
        }
    }
    red[tid] = sum; __syncthreads();
    #pragma unroll
    for (int s = 128; s > 0; s >>= 1) {
        if (tid < s) red[tid] += red[tid + s];
        __syncthreads();
    }
    const float inv = 1.0f / red[0];

    for (int t = tid; t < lo; t += 256)          sr[t] = 0.0f;
    for (int t = hi + 1 + tid; t < TT; t += 256) sr[t] = 0.0f;
    {
        int j = 0;
        for (int t = lo + tid; t <= hi; t += 256, j++) sr[t] = e[j] * inv;
    }
}

// ---------------------------------------------------------------------------
extern "C" void kernel_launch(void* const* d_in, const int* in_sizes, int n_in,
                              void* d_out, int out_size)
{
    const float* x  = (const float*)d_in[0];   // (L, d)
    const float* Wq = (const float*)d_in[1];   // (d, d)
    const float* Pk = (const float*)d_in[2];   // (1, T, d)
    const float* Pv = (const float*)d_in[3];   // (1, T, d)
    float* out = (float*)d_out;                // (1, L, d)

    float *Q, *S, *VT;
    cudaGetSymbolAddress((void**)&Q,  g_Q);
    cudaGetSymbolAddress((void**)&S,  g_S);
    cudaGetSymbolAddress((void**)&VT, g_VT);

    cudaFuncSetAttribute(tf32_gemm_nt<false, false>,
                         cudaFuncAttributeMaxDynamicSharedMemorySize, SMEM_B);
    cudaFuncSetAttribute(tf32_gemm_nt<true, false>,
                         cudaFuncAttributeMaxDynamicSharedMemorySize, SMEM_B);
    cudaFuncSetAttribute(tf32_gemm_nt<false, true>,
                         cudaFuncAttributeMaxDynamicSharedMemorySize, SMEM_B);

    const float scale = 1.0f / sqrtf((float)DD);

    // 0) Pv^T for NT layout of GEMM3
    k_transpose<<<dim3(TT / 32, DD / 32), dim3(32, 8)>>>(Pv, VT);

    // 1) Q = (x @ Wq^T) * scale
    tf32_gemm_nt<false, false><<<dim3(DD / 128, LQ / 128), 256, SMEM_B>>>(
        x, Wq, Q, DD, DD, scale);

    // 2) S = Q @ Pk^T (band tiles only; masked region handled by softmax)
    tf32_gemm_nt<true, false><<<dim3(TT / 128, LQ / 128), 256, SMEM_B>>>(
        Q, Pk, S, TT, DD, 1.0f);

    // 3) banded softmax in place (exact zeros outside window)
    k_softmax<<<LQ, 256>>>(S);

    // 4) y = P @ PvT^T, K restricted to band union per row-block
    tf32_gemm_nt<false, true><<<dim3(DD / 128, LQ / 128), 256, SMEM_B>>>(
        S, VT, out, DD, TT, 1.0f);
}

// round 12
// speedup vs baseline: 6.0824x; 1.7048x over previous
#include <cuda_runtime.h>
#include <cuda_fp16.h>
#include <math.h>
#include <stdint.h>

#define LQ  4096
#define DD  2048
#define TT  4096
#define WIN 1024

// ---------------- scratch (device globals; no allocation APIs) --------------
__device__ alignas(16) __half g_x16[(size_t)LQ * DD];   // x       fp16 (16MB)
__device__ alignas(16) __half g_w16[(size_t)DD * DD];   // Wq      fp16 ( 8MB)
__device__ alignas(16) __half g_k16[(size_t)TT * DD];   // Pk      fp16 (16MB)
__device__ alignas(16) __half g_q16[(size_t)LQ * DD];   // Q*scale fp16 (16MB)
__device__ alignas(16) __half g_p16[(size_t)LQ * TT];   // probs   fp16 (32MB)
__device__ alignas(16) __half g_v16[(size_t)DD * TT];   // Pv^T    fp16 (16MB)
__device__ float g_S[(size_t)LQ * TT];                  // scores  fp32 (64MB)

// ---------------- PTX helpers ----------------------------------------------
__device__ __forceinline__ uint32_t smem_u32(const void* p) {
    uint32_t a;
    asm("{ .reg .u64 t; cvta.to.shared.u64 t, %1; cvt.u32.u64 %0, t; }"
        : "=r"(a) : "l"(p));
    return a;
}
#define CP_ASYNC16(dst, src) \
    asm volatile("cp.async.cg.shared.global [%0], [%1], 16;" :: "r"(dst), "l"(src))
#define CP_COMMIT() asm volatile("cp.async.commit_group;" ::: "memory")
#define CP_WAIT(n)  asm volatile("cp.async.wait_group %0;" :: "n"(n) : "memory")

#define LDSM4(r0, r1, r2, r3, addr) \
    asm volatile("ldmatrix.sync.aligned.m8n8.x4.shared.b16 {%0,%1,%2,%3}, [%4];" \
                 : "=r"(r0), "=r"(r1), "=r"(r2), "=r"(r3) : "r"(addr))

__device__ __forceinline__ void mma_f16(float* c, const uint32_t* a, const uint32_t* b) {
    asm volatile("mma.sync.aligned.m16n8k16.row.col.f32.f16.f16.f32 "
                 "{%0,%1,%2,%3}, {%4,%5,%6,%7}, {%8,%9}, {%0,%1,%2,%3};"
                 : "+f"(c[0]), "+f"(c[1]), "+f"(c[2]), "+f"(c[3])
                 : "r"(a[0]), "r"(a[1]), "r"(a[2]), "r"(a[3]),
                   "r"(b[0]), "r"(b[1]));
}

// ---------------- fp16 NT GEMM: C[M,N] = A[M,K] * B[N,K]^T ------------------
// 128x128 CTA tile, BK=32, cp.async double buffer, 256 thr, 8 warps of 64x32.
// Smem rows padded to stride 40 halves (80B) -> conflict-free ldmatrix.
// BAND   : skip tiles fully outside sliding window (scores GEMM).
// KRANGE : restrict K loop to band union per row-block (output GEMM).
// OUTH   : write fp16 output (Q) with scale; else fp32.
static constexpr int HSTR   = 40;                 // halves per smem row
static constexpr int TILE_H = 128 * HSTR;         // halves per tile (A or B)
static constexpr int BUF_H  = 2 * TILE_H;         // A+B per buffer
static constexpr int SMEM_B = 2 * BUF_H * 2;      // bytes: 40960

template<bool BAND, bool KRANGE, bool OUTH>
__global__ __launch_bounds__(256, 2)
void h_gemm_nt(const __half* __restrict__ A, const __half* __restrict__ B,
               float* __restrict__ Cf, __half* __restrict__ Ch,
               int Ntot, int Ktot, float scale)
{
    const int bm = blockIdx.y, bn = blockIdx.x;
    if (BAND) {
        const int r0 = bm << 7, c0 = bn << 7;
        int dist = 0;
        if (c0 > r0 + 127)      dist = c0 - (r0 + 127);
        else if (r0 > c0 + 127) dist = r0 - (c0 + 127);
        if (dist >= WIN) return;
    }
    int k0 = 0, kend = Ktot;
    if (KRANGE) {
        k0 = bm * 128 - (WIN - 1); if (k0 < 0) k0 = 0; k0 &= ~31;
        kend = bm * 128 + 127 + WIN;
        kend = (kend + 31) & ~31; if (kend > Ktot) kend = Ktot;
    }
    const int nT = (kend - k0) >> 5;

    extern __shared__ __half sm[];
    const int tid = threadIdx.x, lane = tid & 31, w = tid >> 5;
    const int wm = (w & 1) * 64, wn = (w >> 1) * 32;

    const __half* Ag = A + (size_t)(bm * 128) * Ktot + k0;
    const __half* Bg = B + (size_t)(bn * 128) * Ktot + k0;

    // staging map: 16B chunk -> (row = tid>>2 (+64), c = tid&3)
    const int srow = tid >> 2, sc = tid & 3;

    auto stage = [&](int t, int buf) {
        __half* As = sm + buf * BUF_H;
        __half* Bs = As + TILE_H;
        const int kb = t << 5;
        #pragma unroll
        for (int i = 0; i < 2; i++) {
            const int r = srow + i * 64;
            uint32_t da = smem_u32(As + r * HSTR + sc * 8);
            uint32_t db = smem_u32(Bs + r * HSTR + sc * 8);
            CP_ASYNC16(da, Ag + (size_t)r * Ktot + kb + sc * 8);
            CP_ASYNC16(db, Bg + (size_t)r * Ktot + kb + sc * 8);
        }
        CP_COMMIT();
    };

    float acc[4][4][4] = {};
    const int lr = lane & 7, ls = lane >> 3;   // ldmatrix lane decomposition

    stage(0, 0);

    for (int t = 0; t < nT; t++) {
        const int buf = t & 1;
        if (t + 1 < nT) { stage(t + 1, buf ^ 1); CP_WAIT(1); }
        else            { CP_WAIT(0); }
        __syncthreads();

        const __half* As = sm + buf * BUF_H;
        const __half* Bs = As + TILE_H;

        // B fragments: one x4 per ni covers both k-steps
        uint32_t bfr[4][4];
        #pragma unroll
        for (int ni = 0; ni < 4; ni++) {
            uint32_t ad = smem_u32(Bs + (wn + ni * 8 + lr) * HSTR + ls * 8);
            LDSM4(bfr[ni][0], bfr[ni][1], bfr[ni][2], bfr[ni][3], ad);
        }
        #pragma unroll
        for (int ks = 0; ks < 2; ks++) {
            uint32_t af[4][4];
            #pragma unroll
            for (int mi = 0; mi < 4; mi++) {
                uint32_t ad = smem_u32(As + (wm + mi * 16 + lr + (ls & 1) * 8) * HSTR
                                          + ks * 16 + (ls >> 1) * 8);
                LDSM4(af[mi][0], af[mi][1], af[mi][2], af[mi][3], ad);
            }
            #pragma unroll
            for (int mi = 0; mi < 4; mi++)
                #pragma unroll
                for (int ni = 0; ni < 4; ni++)
                    mma_f16(acc[mi][ni], af[mi], &bfr[ni][ks * 2]);
        }
        __syncthreads();
    }

    // epilogue: c0,c1 at (g, 2t..2t+1); c2,c3 at (g+8, ...)
    #pragma unroll
    for (int mi = 0; mi < 4; mi++) {
        const int row = bm * 128 + wm + mi * 16 + (lane >> 2);
        #pragma unroll
        for (int ni = 0; ni < 4; ni++) {
            const int col = bn * 128 + wn + ni * 8 + 2 * (lane & 3);
            if (OUTH) {
                __half2* p0 = (__half2*)(Ch + (size_t)row * Ntot + col);
                __half2* p1 = (__half2*)(Ch + (size_t)(row + 8) * Ntot + col);
                *p0 = __floats2half2_rn(acc[mi][ni][0] * scale, acc[mi][ni][1] * scale);
                *p1 = __floats2half2_rn(acc[mi][ni][2] * scale, acc[mi][ni][3] * scale);
            } else {
                float2* p0 = (float2*)(Cf + (size_t)row * Ntot + col);
                float2* p1 = (float2*)(Cf + (size_t)(row + 8) * Ntot + col);
                *p0 = make_float2(acc[mi][ni][0] * scale, acc[mi][ni][1] * scale);
                *p1 = make_float2(acc[mi][ni][2] * scale, acc[mi][ni][3] * scale);
            }
        }
    }
}

// ---------------- fp32 -> fp16 copy -----------------------------------------
__global__ __launch_bounds__(256)
void k_tohalf(const float* __restrict__ in, __half* __restrict__ out, int n4)
{
    for (int i = blockIdx.x * 256 + threadIdx.x; i < n4; i += gridDim.x * 256) {
        float4 v = ((const float4*)in)[i];
        __half2 h0 = __floats2half2_rn(v.x, v.y);
        __half2 h1 = __floats2half2_rn(v.z, v.w);
        ((__half2*)out)[2 * i]     = h0;
        ((__half2*)out)[2 * i + 1] = h1;
    }
}

// ---------------- Pv [T][D] -> Pv^T [D][T] fp16 -----------------------------
__global__ __launch_bounds__(256)
void k_transpose_h(const float* __restrict__ in, __half* __restrict__ out)
{
    __shared__ float t[32][33];
    const int bx = blockIdx.x;   // T tile
    const int by = blockIdx.y;   // D tile
    const int tx = threadIdx.x, ty0 = threadIdx.y;
    #pragma unroll
    for (int i = 0; i < 4; i++) {
        int ty = ty0 + i * 8;
        t[ty][tx] = in[(size_t)(bx * 32 + ty) * DD + by * 32 + tx];
    }
    __syncthreads();
    #pragma unroll
    for (int i = 0; i < 4; i++) {
        int ty = ty0 + i * 8;
        out[(size_t)(by * 32 + ty) * TT + bx * 32 + tx] = __float2half_rn(t[tx][ty]);
    }
}

// ---------------- banded softmax: fp32 scores -> fp16 probs ------------------
// Zeros are written only inside the K-range union that GEMM3 will read.
__global__ __launch_bounds__(256)
void k_softmax(const float* __restrict__ S, __half* __restrict__ P)
{
    const int row = blockIdx.x;
    const int lo  = max(0, row - (WIN - 1));
    const int hi  = min(TT - 1, row + (WIN - 1));
    const int bm  = row >> 7;
    int k0u = bm * 128 - (WIN - 1); if (k0u < 0) k0u = 0; k0u &= ~31;
    int keu = bm * 128 + 127 + WIN; keu = (keu + 31) & ~31; if (keu > TT) keu = TT;

    const float* sr = S + (size_t)row * TT;
    __half* pr = P + (size_t)row * TT;

    __shared__ float red[256];
    const int tid = threadIdx.x;

    float mx = -3.402823e38f;
    for (int t = lo + tid; t <= hi; t += 256) mx = fmaxf(mx, sr[t]);
    red[tid] = mx; __syncthreads();
    #pragma unroll
    for (int s = 128; s > 0; s >>= 1) {
        if (tid < s) red[tid] = fmaxf(red[tid], red[tid + s]);
        __syncthreads();
    }
    mx = red[0]; __syncthreads();

    float e[8];
    float sum = 0.0f;
    {
        int j = 0;
        for (int t = lo + tid; t <= hi; t += 256, j++) {
            float ev = __expf(sr[t] - mx);
            e[j] = ev; sum += ev;
        }
    }
    red[tid] = sum; __syncthreads();
    #pragma unroll
    for (int s = 128; s > 0; s >>= 1) {
        if (tid < s) red[tid] += red[tid + s];
        __syncthreads();
    }
    const float inv = 1.0f / red[0];

    const __half z = __float2half_rn(0.0f);
    for (int t = k0u + tid; t < lo; t += 256)     pr[t] = z;
    for (int t = hi + 1 + tid; t < keu; t += 256) pr[t] = z;
    {
        int j = 0;
        for (int t = lo + tid; t <= hi; t += 256, j++)
            pr[t] = __float2half_rn(e[j] * inv);
    }
}

// ---------------------------------------------------------------------------
extern "C" void kernel_launch(void* const* d_in, const int* in_sizes, int n_in,
                              void* d_out, int out_size)
{
    const float* x  = (const float*)d_in[0];   // (L, d)
    const float* Wq = (const float*)d_in[1];   // (d, d)
    const float* Pk = (const float*)d_in[2];   // (1, T, d)
    const float* Pv = (const float*)d_in[3];   // (1, T, d)
    float* out = (float*)d_out;                // (1, L, d)

    __half *x16, *w16, *k16, *q16, *p16, *v16;
    float* S;
    cudaGetSymbolAddress((void**)&x16, g_x16);
    cudaGetSymbolAddress((void**)&w16, g_w16);
    cudaGetSymbolAddress((void**)&k16, g_k16);
    cudaGetSymbolAddress((void**)&q16, g_q16);
    cudaGetSymbolAddress((void**)&p16, g_p16);
    cudaGetSymbolAddress((void**)&v16, g_v16);
    cudaGetSymbolAddress((void**)&S,   g_S);

    cudaFuncSetAttribute(h_gemm_nt<false, false, true>,
                         cudaFuncAttributeMaxDynamicSharedMemorySize, SMEM_B);
    cudaFuncSetAttribute(h_gemm_nt<true, false, false>,
                         cudaFuncAttributeMaxDynamicSharedMemorySize, SMEM_B);
    cudaFuncSetAttribute(h_gemm_nt<false, true, false>,
                         cudaFuncAttributeMaxDynamicSharedMemorySize, SMEM_B);

    const float scale = 1.0f / sqrtf((float)DD);

    // 0) operand conversions
    k_tohalf<<<1024, 256>>>(x,  x16, LQ * DD / 4);
    k_tohalf<<<1024, 256>>>(Wq, w16, DD * DD / 4);
    k_tohalf<<<1024, 256>>>(Pk, k16, TT * DD / 4);
    k_transpose_h<<<dim3(TT / 32, DD / 32), dim3(32, 8)>>>(Pv, v16);

    // 1) Q = (x @ Wq^T) * scale  -> fp16
    h_gemm_nt<false, false, true><<<dim3(DD / 128, LQ / 128), 256, SMEM_B>>>(
        x16, w16, nullptr, q16, DD, DD, scale);

    // 2) S = Q @ Pk^T (band tiles only) -> fp32
    h_gemm_nt<true, false, false><<<dim3(TT / 128, LQ / 128), 256, SMEM_B>>>(
        q16, k16, S, nullptr, TT, DD, 1.0f);

    // 3) banded softmax -> fp16 probs (zeros inside G3 K-range union)
    k_softmax<<<LQ, 256>>>(S, p16);

    // 4) y = P @ PvT^T, K restricted to band union per row-block -> fp32 out
    h_gemm_nt<false, true, false><<<dim3(DD / 128, LQ / 128), 256, SMEM_B>>>(
        p16, v16, out, nullptr, DD, TT, 1.0f);
}